// round 15
// baseline (speedup 1.0000x reference)
#include <cuda_runtime.h>
#include <cuda_fp16.h>
#include <math.h>
#include <stdint.h>

#define BB 2
#define LL 2048
#define DD 1024
#define HH 16
#define DKK 64
#define DFF 4096
#define MM (BB*LL)   // 4096
#define EPS 1e-5f

// ================= helpers =================
__device__ __forceinline__ uint32_t smem_u32(const void* p) {
    uint32_t a;
    asm("{ .reg .u64 t; cvta.to.shared.u64 t, %1; cvt.u32.u64 %0, t; }" : "=r"(a) : "l"(p));
    return a;
}

#define LDSM_X4(r, addr) \
    asm volatile("ldmatrix.sync.aligned.m8n8.x4.shared.b16 {%0,%1,%2,%3}, [%4];" \
        : "=r"((r)[0]), "=r"((r)[1]), "=r"((r)[2]), "=r"((r)[3]) : "r"(addr))
#define LDSM_X4T(r, addr) \
    asm volatile("ldmatrix.sync.aligned.m8n8.x4.trans.shared.b16 {%0,%1,%2,%3}, [%4];" \
        : "=r"((r)[0]), "=r"((r)[1]), "=r"((r)[2]), "=r"((r)[3]) : "r"(addr))

#define MMAH16816(d, a, b0, b1) \
    asm volatile("mma.sync.aligned.m16n8k16.row.col.f32.f16.f16.f32 " \
        "{%0,%1,%2,%3}, {%4,%5,%6,%7}, {%8,%9}, {%0,%1,%2,%3};" \
        : "+f"((d)[0]), "+f"((d)[1]), "+f"((d)[2]), "+f"((d)[3]) \
        : "r"((a)[0]), "r"((a)[1]), "r"((a)[2]), "r"((a)[3]), "r"(b0), "r"(b1))

#define STS128U(addr, a, b, c, d) \
    asm volatile("st.shared.v4.b32 [%0], {%1, %2, %3, %4};" \
                 :: "r"((uint32_t)(addr)), "r"(a), "r"(b), "r"(c), "r"(d) : "memory")

__device__ __forceinline__ void cpa16(uint32_t dst, const void* src) {
    asm volatile("cp.async.cg.shared.global [%0], [%1], 16;" :: "r"(dst), "l"(src));
}
#define CP_COMMIT() asm volatile("cp.async.commit_group;" ::: "memory")
#define CP_WAIT2()  asm volatile("cp.async.wait_group 2;" ::: "memory")

__device__ __forceinline__ uint32_t packh(float x0, float x1) {
    __half2 h = __floats2half2_rn(x0, x1);
    return *reinterpret_cast<uint32_t*>(&h);
}

#define SCQ (0.125f * 1.4426950408889634f)   // 1/sqrt(64) * log2(e)

// ================= scratch =================
__device__ float g_vsuf[BB*HH*LL*DKK];
__device__ float g_y1  [BB*LL*DD];
__device__ float g_part[BB*256*2];
__device__ float g_stats[BB*2];

// fp16 operands
__device__ __half g_xh  [BB*LL*DD];
__device__ __half g_lnyh[BB*LL*DD];
__device__ __half g_ln1h[BB*LL*DD];
__device__ __half g_qh  [BB*LL*DD];
__device__ __half g_kh  [BB*LL*DD];
__device__ __half g_vh  [BB*LL*DD];
__device__ __half g_atth[BB*LL*DD];
__device__ __half g_hh  [BB*LL*DFF];
__device__ __half g_wqh[DD*DD];
__device__ __half g_wkh[DD*DD];
__device__ __half g_wvh[DD*DD];
__device__ __half g_woh[DD*DD];
__device__ __half g_w1h[DD*DFF];
__device__ __half g_w2h[DFF*DD];

// ================= fused fp32 -> fp16 converts (one launch) =================
__global__ void __launch_bounds__(256)
convert_all(const float* __restrict__ x,  const float* __restrict__ Wq,
            const float* __restrict__ Wk, const float* __restrict__ Wv,
            const float* __restrict__ Wo, const float* __restrict__ W1,
            const float* __restrict__ W2) {
    const float4* src; uint2* dst; int n4;
    switch (blockIdx.y) {
        case 0: src = (const float4*)x;  dst = (uint2*)g_xh;  n4 = BB*LL*DD/4; break;
        case 1: src = (const float4*)Wq; dst = (uint2*)g_wqh; n4 = DD*DD/4;    break;
        case 2: src = (const float4*)Wk; dst = (uint2*)g_wkh; n4 = DD*DD/4;    break;
        case 3: src = (const float4*)Wv; dst = (uint2*)g_wvh; n4 = DD*DD/4;    break;
        case 4: src = (const float4*)Wo; dst = (uint2*)g_woh; n4 = DD*DD/4;    break;
        case 5: src = (const float4*)W1; dst = (uint2*)g_w1h; n4 = DD*DFF/4;   break;
        default: src = (const float4*)W2; dst = (uint2*)g_w2h; n4 = DFF*DD/4;  break;
    }
    for (int i = blockIdx.x*blockDim.x + threadIdx.x; i < n4; i += gridDim.x*blockDim.x) {
        float4 v = src[i];
        dst[i] = make_uint2(packh(v.x, v.y), packh(v.z, v.w));
    }
}

// ================= LayerNorm over (L,D) jointly =================
__global__ void ln_reduce1(const float* __restrict__ x) {
    const int batch = blockIdx.y;
    const int chunk4 = (LL*DD)/(256*4);      // float4s per block
    const float4* xp = (const float4*)(x + (size_t)batch*LL*DD) + (size_t)blockIdx.x*chunk4;
    float s = 0.f, s2 = 0.f;
    for (int i = threadIdx.x; i < chunk4; i += 256) {
        float4 v = xp[i];
        s  += v.x + v.y + v.z + v.w;
        s2 += v.x*v.x + v.y*v.y + v.z*v.z + v.w*v.w;
    }
    __shared__ float sh[256], sh2[256];
    sh[threadIdx.x] = s; sh2[threadIdx.x] = s2;
    __syncthreads();
    for (int o = 128; o > 0; o >>= 1) {
        if (threadIdx.x < o) { sh[threadIdx.x] += sh[threadIdx.x+o]; sh2[threadIdx.x] += sh2[threadIdx.x+o]; }
        __syncthreads();
    }
    if (threadIdx.x == 0) {
        g_part[(batch*256 + blockIdx.x)*2 + 0] = sh[0];
        g_part[(batch*256 + blockIdx.x)*2 + 1] = sh2[0];
    }
}

__global__ void ln_reduce2() {
    const int batch = blockIdx.x;
    __shared__ float sh[256], sh2[256];
    sh[threadIdx.x]  = g_part[(batch*256 + threadIdx.x)*2 + 0];
    sh2[threadIdx.x] = g_part[(batch*256 + threadIdx.x)*2 + 1];
    __syncthreads();
    for (int o = 128; o > 0; o >>= 1) {
        if (threadIdx.x < o) { sh[threadIdx.x] += sh[threadIdx.x+o]; sh2[threadIdx.x] += sh2[threadIdx.x+o]; }
        __syncthreads();
    }
    if (threadIdx.x == 0) {
        const float inv = 1.0f / (float)(LL*DD);
        float mu  = sh[0]  * inv;
        float var = sh2[0] * inv - mu*mu;
        g_stats[batch*2 + 0] = mu;
        g_stats[batch*2 + 1] = rsqrtf(var + EPS);
    }
}

__global__ void ln_apply_h(const float* __restrict__ x, const float* __restrict__ w,
                           const float* __restrict__ b, __half* __restrict__ out) {
    const int batch = blockIdx.y;
    const float mu   = g_stats[batch*2 + 0];
    const float rstd = g_stats[batch*2 + 1];
    const long base = (long)batch*LL*DD;
    const int n4 = LL*DD/4;
    for (int i = blockIdx.x*blockDim.x + threadIdx.x; i < n4; i += gridDim.x*blockDim.x) {
        const long idx = (long)i*4;
        float4 xv = *(const float4*)(x + base + idx);
        float4 wv = *(const float4*)(w + idx);
        float4 bv = *(const float4*)(b + idx);
        float v0 = (xv.x - mu)*rstd*wv.x + bv.x;
        float v1 = (xv.y - mu)*rstd*wv.y + bv.y;
        float v2 = (xv.z - mu)*rstd*wv.z + bv.z;
        float v3 = (xv.w - mu)*rstd*wv.w + bv.w;
        *(uint2*)(out + base + idx) = make_uint2(packh(v0, v1), packh(v2, v3));
    }
}

// ================= fp16 cp.async GEMM (128x128, warp 64x32, 4-stage) =================
#define ASTR 48
#define OFF_A1 6144
#define OFF_B  12288
#define BSTR 272
#define BSUB 4352
#define STAGE 20992
#define SMEM_GEMM4 (4*STAGE)

template<int EPI, int OUTH>
__device__ __forceinline__ void gemm_body(
    const __half* __restrict__ A, const __half* __restrict__ W,
    const float* __restrict__ bias, const float* __restrict__ R,
    float* __restrict__ C, __half* __restrict__ Ch, int N, int K, char* sm)
{
    const uint32_t sbase = smem_u32(sm);
    const int t = threadIdx.x;
    const int lane = t & 31, wid = t >> 5;
    const int g = lane >> 2, tig = lane & 3;
    const int wm = wid >> 2, wn = wid & 3;
    const int bm = blockIdx.y * 128, bn = blockIdx.x * 128;

    const int ar = t >> 1, aq = t & 1;
    const int br = t >> 4, bc = (t & 15) * 8;

    const __half* Agp = A + (size_t)(bm + ar) * K + aq * 8;
    const __half* Bgp = W + (size_t)br * N + bn + bc;

    const uint32_t a_sts = (uint32_t)ar * ASTR + (uint32_t)aq * 16;
    const uint32_t b_sts = (uint32_t)br * BSTR + (uint32_t)bc * 2;

    const uint32_t a_base = sbase + (uint32_t)(wm*64 + (lane & 15)) * ASTR + ((lane >> 4) & 1) * 16;
    const uint32_t b_base = sbase + OFF_B + (uint32_t)(lane & 15) * BSTR + (uint32_t)wn * 64 + ((lane >> 4) & 1) * 16;

    float acc[4][4][4];
    #pragma unroll
    for (int i = 0; i < 4; i++)
        #pragma unroll
        for (int j = 0; j < 4; j++)
            #pragma unroll
            for (int c = 0; c < 4; c++) acc[i][j][c] = 0.f;

    const int nk = K / 32;

    auto issue = [&](int s) {
        const uint32_t sb = sbase + (uint32_t)(s & 3) * STAGE;
        const int k0 = s * 32;
        cpa16(sb + a_sts,          Agp + k0);
        cpa16(sb + OFF_A1 + a_sts, Agp + k0 + 16);
        cpa16(sb + OFF_B + b_sts,        Bgp + (size_t)k0 * N);
        cpa16(sb + OFF_B + b_sts + BSUB, Bgp + (size_t)(k0 + 16) * N);
    };

    issue(0); CP_COMMIT();
    if (nk > 1) issue(1);
    CP_COMMIT();
    if (nk > 2) issue(2);
    CP_COMMIT();

    for (int s = 0; s < nk; s++) {
        CP_WAIT2();
        __syncthreads();
        if (s + 3 < nk) issue(s + 3);
        CP_COMMIT();

        const uint32_t so = (uint32_t)(s & 3) * STAGE;
        #pragma unroll
        for (int ks = 0; ks < 2; ks++) {
            uint32_t ah[4][4], bf[2][4];
            #pragma unroll
            for (int i = 0; i < 4; i++)
                LDSM_X4(ah[i], a_base + so + ks*OFF_A1 + i*(16*ASTR));
            #pragma unroll
            for (int j2 = 0; j2 < 2; j2++)
                LDSM_X4T(bf[j2], b_base + so + ks*BSUB + j2*32);
            #pragma unroll
            for (int i = 0; i < 4; i++)
                #pragma unroll
                for (int j = 0; j < 4; j++)
                    MMAH16816(acc[i][j], ah[i], bf[j>>1][(j&1)*2], bf[j>>1][(j&1)*2+1]);
        }
    }

    #pragma unroll
    for (int i = 0; i < 4; i++) {
        const int row0 = bm + wm*64 + i*16 + g;
        #pragma unroll
        for (int j = 0; j < 4; j++) {
            const int col0 = bn + wn*32 + j*8 + 2*tig;
            float2 bs = *(const float2*)(bias + col0);
            float2 c01 = make_float2(acc[i][j][0] + bs.x, acc[i][j][1] + bs.y);
            float2 c23 = make_float2(acc[i][j][2] + bs.x, acc[i][j][3] + bs.y);
            if (EPI == 1) {
                c01.x = fmaxf(c01.x, 0.f); c01.y = fmaxf(c01.y, 0.f);
                c23.x = fmaxf(c23.x, 0.f); c23.y = fmaxf(c23.y, 0.f);
            }
            if (EPI == 2) {
                float2 r0 = *(const float2*)(R + (size_t)row0 * N + col0);
                float2 r1 = *(const float2*)(R + (size_t)(row0+8) * N + col0);
                c01.x += r0.x; c01.y += r0.y;
                c23.x += r1.x; c23.y += r1.y;
            }
            if (EPI == 3) {
                c01.x *= SCQ; c01.y *= SCQ; c23.x *= SCQ; c23.y *= SCQ;
            }
            if (OUTH == 0) {
                *(float2*)(C + (size_t)row0 * N + col0)     = c01;
                *(float2*)(C + (size_t)(row0+8) * N + col0) = c23;
            } else {
                *(uint32_t*)(Ch + (size_t)row0 * N + col0)     = packh(c01.x, c01.y);
                *(uint32_t*)(Ch + (size_t)(row0+8) * N + col0) = packh(c23.x, c23.y);
            }
        }
    }
}

template<int EPI, int OUTH>
__global__ void __launch_bounds__(256)
tgemm(const __half* __restrict__ A, const __half* __restrict__ W,
      const float* __restrict__ bias, const float* __restrict__ R,
      float* __restrict__ C, __half* __restrict__ Ch, int N, int K)
{
    extern __shared__ __align__(128) char sm[];
    gemm_body<EPI, OUTH>(A, W, bias, R, C, Ch, N, K, sm);
}

__global__ void __launch_bounds__(256)
qkv_gemm(const float* __restrict__ bq, const float* __restrict__ bk,
         const float* __restrict__ bv)
{
    extern __shared__ __align__(128) char sm[];
    const int z = blockIdx.z;
    if (z == 0) {
        gemm_body<3,1>(g_xh,   g_wqh, bq, nullptr, nullptr, g_qh, DD, DD, sm);
    } else if (z == 1) {
        gemm_body<0,1>(g_lnyh, g_wkh, bk, nullptr, nullptr, g_kh, DD, DD, sm);
    } else {
        gemm_body<0,1>(g_lnyh, g_wvh, bv, nullptr, nullptr, g_vh, DD, DD, sm);
    }
}

// ================= V suffix sums (fp16 V, 2 blocks per bh) =================
__global__ void __launch_bounds__(1024) vsuffix_kernel() {
    const int bh = blockIdx.x >> 1;
    const int half = blockIdx.x & 1;
    const int b = bh / HH, h = bh % HH;
    const int d = half * 32 + (threadIdx.x & 31);
    const int seg = threadIdx.x >> 5;
    const int SEGK = LL / 32;
    __shared__ float part[32][32];
    const size_t vbase = (size_t)b*LL*DD + (size_t)h*DKK + d;
    const int k0 = seg * SEGK;
    float s = 0.f;
    for (int k = k0; k < k0 + SEGK; k++) s += __half2float(g_vh[vbase + (size_t)k*DD]);
    part[seg][threadIdx.x & 31] = s;
    __syncthreads();
    float acc = 0.f;
    for (int ss = seg + 1; ss < 32; ss++) acc += part[ss][threadIdx.x & 31];
    const size_t sb = (size_t)bh*LL*DKK + d;
    for (int k = k0 + SEGK - 1; k >= k0; k--) {
        g_vsuf[sb + (size_t)k*DKK] = acc;
        acc += __half2float(g_vh[vbase + (size_t)k*DD]);
    }
}

// ================= fp16 flash attention, 128 q-rows x 128-key phases, 8 warps =================
#define TSTR 144
#define QT128 (128*TSTR)
#define CHT   (128*TSTR)

__global__ void __launch_bounds__(256)
fattn_kernel() {
    __shared__ __align__(16) char smr[QT128 + 2*CHT];
    const uint32_t sQ = smem_u32(smr);
    const uint32_t sK = sQ + QT128;
    const uint32_t sV = sK + CHT;

    const int b = blockIdx.z, h = blockIdx.y;
    const int qt = gridDim.x - 1 - blockIdx.x;   // heavy tiles first
    const int q0 = qt * 128;
    const int t = threadIdx.x, w = t >> 5, lane = t & 31;
    const int g = lane >> 2, tg = lane & 3;
    const int r = t >> 1, hf = t & 1;

    // ---- load Q tile (128 rows; fp16, pre-scaled) ----
    {
        const __half* qp = g_qh + ((size_t)(b*LL + q0 + r))*DD + h*DKK + hf*32;
        const uint32_t dq = sQ + (uint32_t)r*TSTR + hf*64;
        uint4 v0 = *(const uint4*)(qp);
        uint4 v1 = *(const uint4*)(qp + 8);
        uint4 v2 = *(const uint4*)(qp + 16);
        uint4 v3 = *(const uint4*)(qp + 24);
        STS128U(dq,      v0.x, v0.y, v0.z, v0.w);
        STS128U(dq + 16, v1.x, v1.y, v1.z, v1.w);
        STS128U(dq + 32, v2.x, v2.y, v2.z, v2.w);
        STS128U(dq + 48, v3.x, v3.y, v3.z, v3.w);
    }
    __syncthreads();

    const int mi = lane >> 3, li = lane & 7;
    uint32_t qh[4][4];
    {
        const uint32_t ro = (uint32_t)(w*16 + ((mi&1)<<3) + li) * TSTR + (uint32_t)((mi>>1)<<4);
        #pragma unroll
        for (int kc4 = 0; kc4 < 4; kc4++)
            LDSM_X4(qh[kc4], sQ + ro + kc4*32);
    }

    float oacc[8][4];
    #pragma unroll
    for (int f = 0; f < 8; f++)
        #pragma unroll
        for (int c = 0; c < 4; c++) oacc[f][c] = 0.f;
    float ls0 = 0.f, ls1 = 0.f;

    const int nch = qt + 1;                  // 128-key phases
    const int wrow_max = q0 + w*16 + 15;

    for (int ci = 0; ci < nch; ci++) {
        const int kc = ci * 128;
        __syncthreads();
        // ---- load K and V phase (128 rows; same pattern as Q loader) ----
        {
            const size_t gbase = ((size_t)(b*LL + kc + r))*DD + h*DKK + hf*32;
            const __half* kp = g_kh + gbase;
            const uint32_t dk = sK + (uint32_t)r*TSTR + hf*64;
            uint4 v0 = *(const uint4*)(kp);
            uint4 v1 = *(const uint4*)(kp + 8);
            uint4 v2 = *(const uint4*)(kp + 16);
            uint4 v3 = *(const uint4*)(kp + 24);
            STS128U(dk,      v0.x, v0.y, v0.z, v0.w);
            STS128U(dk + 16, v1.x, v1.y, v1.z, v1.w);
            STS128U(dk + 32, v2.x, v2.y, v2.z, v2.w);
            STS128U(dk + 48, v3.x, v3.y, v3.z, v3.w);
            const __half* vp = g_vh + gbase;
            const uint32_t dv = sV + (uint32_t)r*TSTR + hf*64;
            v0 = *(const uint4*)(vp);
            v1 = *(const uint4*)(vp + 8);
            v2 = *(const uint4*)(vp + 16);
            v3 = *(const uint4*)(vp + 24);
            STS128U(dv,      v0.x, v0.y, v0.z, v0.w);
            STS128U(dv + 16, v1.x, v1.y, v1.z, v1.w);
            STS128U(dv + 32, v2.x, v2.y, v2.z, v2.w);
            STS128U(dv + 48, v3.x, v3.y, v3.z, v3.w);
        }
        __syncthreads();

        // ---- two 64-key sub-chunks ----
        #pragma unroll
        for (int sub = 0; sub < 2; sub++) {
            const int kcs = kc + sub*64;
            if (kcs > wrow_max) continue;
            const uint32_t sKs = sK + (uint32_t)sub*(64*TSTR);
            const uint32_t sVs = sV + (uint32_t)sub*(64*TSTR);

            float sacc[8][4];
            #pragma unroll
            for (int f = 0; f < 8; f++)
                #pragma unroll
                for (int c = 0; c < 4; c++) sacc[f][c] = 0.f;

            #pragma unroll
            for (int kc4 = 0; kc4 < 4; kc4++) {
                uint32_t bk[8][2];
                #pragma unroll
                for (int j2 = 0; j2 < 4; j2++) {
                    uint32_t tmp[4];
                    const uint32_t ro = (uint32_t)((2*j2 + (mi>>1))*8 + li) * TSTR
                                      + (uint32_t)(kc4*32 + (mi&1)*16);
                    LDSM_X4(tmp, sKs + ro);
                    bk[2*j2][0] = tmp[0]; bk[2*j2][1] = tmp[1];
                    bk[2*j2+1][0] = tmp[2]; bk[2*j2+1][1] = tmp[3];
                }
                #pragma unroll
                for (int f = 0; f < 8; f++) MMAH16816(sacc[f], qh[kc4], bk[f][0], bk[f][1]);
            }

            const int row0 = q0 + w*16 + g;
            if (kcs + 63 > row0 + 8) {
                #pragma unroll
                for (int f = 0; f < 8; f++) {
                    const int col = kcs + f*8 + 2*tg;
                    sacc[f][0] = (col   <= row0)   ? exp2f(sacc[f][0]) : 0.f;
                    sacc[f][1] = (col+1 <= row0)   ? exp2f(sacc[f][1]) : 0.f;
                    sacc[f][2] = (col   <= row0+8) ? exp2f(sacc[f][2]) : 0.f;
                    sacc[f][3] = (col+1 <= row0+8) ? exp2f(sacc[f][3]) : 0.f;
                }
            } else {
                #pragma unroll
                for (int f = 0; f < 8; f++) {
                    sacc[f][0] = exp2f(sacc[f][0]);
                    sacc[f][1] = exp2f(sacc[f][1]);
                    sacc[f][2] = exp2f(sacc[f][2]);
                    sacc[f][3] = exp2f(sacc[f][3]);
                }
            }
            #pragma unroll
            for (int f = 0; f < 8; f++) {
                ls0 += sacc[f][0] + sacc[f][1];
                ls1 += sacc[f][2] + sacc[f][3];
            }

            #pragma unroll
            for (int kc4 = 0; kc4 < 4; kc4++) {
                uint32_t aP[4];
                aP[0] = packh(sacc[2*kc4][0],   sacc[2*kc4][1]);
                aP[1] = packh(sacc[2*kc4][2],   sacc[2*kc4][3]);
                aP[2] = packh(sacc[2*kc4+1][0], sacc[2*kc4+1][1]);
                aP[3] = packh(sacc[2*kc4+1][2], sacc[2*kc4+1][3]);
                uint32_t bv[8][2];
                #pragma unroll
                for (int j2 = 0; j2 < 4; j2++) {
                    uint32_t tmp[4];
                    const uint32_t ro = (uint32_t)(kc4*16 + (mi&1)*8 + li) * TSTR
                                      + (uint32_t)((2*j2 + (mi>>1))*16);
                    LDSM_X4T(tmp, sVs + ro);
                    bv[2*j2][0] = tmp[0]; bv[2*j2][1] = tmp[1];
                    bv[2*j2+1][0] = tmp[2]; bv[2*j2+1][1] = tmp[3];
                }
                #pragma unroll
                for (int f = 0; f < 8; f++) MMAH16816(oacc[f], aP, bv[f][0], bv[f][1]);
            }
        }
    }

    ls0 += __shfl_xor_sync(0xffffffffu, ls0, 1);
    ls0 += __shfl_xor_sync(0xffffffffu, ls0, 2);
    ls1 += __shfl_xor_sync(0xffffffffu, ls1, 1);
    ls1 += __shfl_xor_sync(0xffffffffu, ls1, 2);

    const int row0 = q0 + w*16 + g;
    const int row1 = row0 + 8;
    const float inv0 = 1.0f / (ls0 + (float)(LL - 1 - row0));
    const float inv1 = 1.0f / (ls1 + (float)(LL - 1 - row1));

    const size_t vs0 = ((size_t)((b*HH + h)*LL) + row0) * DKK;
    const size_t vs1 = ((size_t)((b*HH + h)*LL) + row1) * DKK;
    const size_t ob0 = ((size_t)(b*LL + row0))*DD + h*DKK;
    const size_t ob1 = ((size_t)(b*LL + row1))*DD + h*DKK;
    #pragma unroll
    for (int f = 0; f < 8; f++) {
        const int col = f*8 + 2*tg;
        float2 t0 = *(const float2*)(g_vsuf + vs0 + col);
        float2 t1 = *(const float2*)(g_vsuf + vs1 + col);
        *(uint32_t*)(g_atth + ob0 + col) = packh((oacc[f][0] + t0.x) * inv0, (oacc[f][1] + t0.y) * inv0);
        *(uint32_t*)(g_atth + ob1 + col) = packh((oacc[f][2] + t1.x) * inv1, (oacc[f][3] + t1.y) * inv1);
    }
}

// ================= launch =================
extern "C" void kernel_launch(void* const* d_in, const int* in_sizes, int n_in,
                              void* d_out, int out_size) {
    const float* x    = (const float*)d_in[0];
    const float* y    = (const float*)d_in[1];
    const float* Wq   = (const float*)d_in[2];
    const float* bq   = (const float*)d_in[3];
    const float* Wk   = (const float*)d_in[4];
    const float* bk   = (const float*)d_in[5];
    const float* Wv   = (const float*)d_in[6];
    const float* bv   = (const float*)d_in[7];
    const float* Wo   = (const float*)d_in[8];
    const float* bo   = (const float*)d_in[9];
    const float* W1   = (const float*)d_in[10];
    const float* b1   = (const float*)d_in[11];
    const float* W2   = (const float*)d_in[12];
    const float* b2   = (const float*)d_in[13];
    const float* ln1w = (const float*)d_in[14];
    const float* ln1b = (const float*)d_in[15];
    const float* ln2w = (const float*)d_in[16];
    const float* ln2b = (const float*)d_in[17];
    float* out = (float*)d_out;

    float *p_y1;
    cudaGetSymbolAddress((void**)&p_y1, g_y1);

    __half *lnyh,*ln1h,*atth,*hh,*woh,*w1h,*w2h;
    cudaGetSymbolAddress((void**)&lnyh, g_lnyh);
    cudaGetSymbolAddress((void**)&ln1h, g_ln1h);
    cudaGetSymbolAddress((void**)&atth, g_atth);
    cudaGetSymbolAddress((void**)&hh,   g_hh);
    cudaGetSymbolAddress((void**)&woh,  g_woh);
    cudaGetSymbolAddress((void**)&w1h,  g_w1h);
    cudaGetSymbolAddress((void**)&w2h,  g_w2h);

    cudaFuncSetAttribute(qkv_gemm,   cudaFuncAttributeMaxDynamicSharedMemorySize, SMEM_GEMM4);
    cudaFuncSetAttribute(tgemm<2,0>, cudaFuncAttributeMaxDynamicSharedMemorySize, SMEM_GEMM4);
    cudaFuncSetAttribute(tgemm<1,1>, cudaFuncAttributeMaxDynamicSharedMemorySize, SMEM_GEMM4);

    // all converts in ONE launch
    convert_all<<<dim3(296, 7), 256>>>(x, Wq, Wk, Wv, Wo, W1, W2);

    // LN1 on y -> fp16 lny
    ln_reduce1<<<dim3(256, BB), 256>>>(y);
    ln_reduce2<<<BB, 256>>>();
    ln_apply_h<<<dim3(296, BB), 256>>>(y, ln1w, ln1b, lnyh);

    // fused Q/K/V (Q scaled fp16, K fp16, V fp16)
    qkv_gemm<<<dim3(DD/128, MM/128, 3), 256, SMEM_GEMM4>>>(bq, bk, bv);

    // suffix sums of V, then attention (writes fp16 attn)
    vsuffix_kernel<<<BB*HH*2, 1024>>>();
    fattn_kernel<<<dim3(LL/128, HH, BB), 256>>>();

    // y1 = y + attn@Wo + bo  (fp32)
    tgemm<2,0><<<dim3(DD/128, MM/128), 256, SMEM_GEMM4>>>(atth, woh, bo, y, p_y1, nullptr, DD, DD);

    // LN2 on y1 -> fp16 lny1
    ln_reduce1<<<dim3(256, BB), 256>>>(p_y1);
    ln_reduce2<<<BB, 256>>>();
    ln_apply_h<<<dim3(296, BB), 256>>>(p_y1, ln2w, ln2b, ln1h);

    // h = relu(lny1@W1 + b1) (fp16 out) ; out = y1 + h@W2 + b2 (fp32)
    tgemm<1,1><<<dim3(DFF/128, MM/128), 256, SMEM_GEMM4>>>(ln1h, w1h, b1, nullptr, nullptr, hh, DFF, DD);
    tgemm<2,0><<<dim3(DD/128,  MM/128), 256, SMEM_GEMM4>>>(hh,   w2h, b2, p_y1,    out, nullptr, DD, DFF);
}

// round 16
// speedup vs baseline: 1.0150x; 1.0150x over previous
#include <cuda_runtime.h>
#include <cuda_fp16.h>
#include <math.h>
#include <stdint.h>

#define BB 2
#define LL 2048
#define DD 1024
#define HH 16
#define DKK 64
#define DFF 4096
#define MM (BB*LL)   // 4096
#define EPS 1e-5f

// ================= helpers =================
__device__ __forceinline__ uint32_t smem_u32(const void* p) {
    uint32_t a;
    asm("{ .reg .u64 t; cvta.to.shared.u64 t, %1; cvt.u32.u64 %0, t; }" : "=r"(a) : "l"(p));
    return a;
}

#define LDSM_X4(r, addr) \
    asm volatile("ldmatrix.sync.aligned.m8n8.x4.shared.b16 {%0,%1,%2,%3}, [%4];" \
        : "=r"((r)[0]), "=r"((r)[1]), "=r"((r)[2]), "=r"((r)[3]) : "r"(addr))
#define LDSM_X4T(r, addr) \
    asm volatile("ldmatrix.sync.aligned.m8n8.x4.trans.shared.b16 {%0,%1,%2,%3}, [%4];" \
        : "=r"((r)[0]), "=r"((r)[1]), "=r"((r)[2]), "=r"((r)[3]) : "r"(addr))

#define MMAH16816(d, a, b0, b1) \
    asm volatile("mma.sync.aligned.m16n8k16.row.col.f32.f16.f16.f32 " \
        "{%0,%1,%2,%3}, {%4,%5,%6,%7}, {%8,%9}, {%0,%1,%2,%3};" \
        : "+f"((d)[0]), "+f"((d)[1]), "+f"((d)[2]), "+f"((d)[3]) \
        : "r"((a)[0]), "r"((a)[1]), "r"((a)[2]), "r"((a)[3]), "r"(b0), "r"(b1))

#define STS128U(addr, a, b, c, d) \
    asm volatile("st.shared.v4.b32 [%0], {%1, %2, %3, %4};" \
                 :: "r"((uint32_t)(addr)), "r"(a), "r"(b), "r"(c), "r"(d) : "memory")

__device__ __forceinline__ void cpa16(uint32_t dst, const void* src) {
    asm volatile("cp.async.cg.shared.global [%0], [%1], 16;" :: "r"(dst), "l"(src));
}
#define CP_COMMIT() asm volatile("cp.async.commit_group;" ::: "memory")
#define CP_WAIT2()  asm volatile("cp.async.wait_group 2;" ::: "memory")

__device__ __forceinline__ uint32_t packh(float x0, float x1) {
    __half2 h = __floats2half2_rn(x0, x1);
    return *reinterpret_cast<uint32_t*>(&h);
}

#define SCQ (0.125f * 1.4426950408889634f)   // 1/sqrt(64) * log2(e)

// ================= scratch =================
__device__ float g_vsuf[BB*HH*LL*DKK];
__device__ float g_y1  [BB*LL*DD];
__device__ float g_part[BB*256*2];
__device__ float g_stats[BB*2];

// fp16 operands
__device__ __half g_xh  [BB*LL*DD];
__device__ __half g_lnyh[BB*LL*DD];
__device__ __half g_ln1h[BB*LL*DD];
__device__ __half g_qh  [BB*LL*DD];
__device__ __half g_kh  [BB*LL*DD];
__device__ __half g_vh  [BB*LL*DD];
__device__ __half g_atth[BB*LL*DD];
__device__ __half g_hh  [BB*LL*DFF];
__device__ __half g_wqh[DD*DD];
__device__ __half g_wkh[DD*DD];
__device__ __half g_wvh[DD*DD];
__device__ __half g_woh[DD*DD];
__device__ __half g_w1h[DD*DFF];
__device__ __half g_w2h[DFF*DD];

// ================= fused fp32 -> fp16 converts (one launch, weighted segments) =================
// grid.y: 0..3 -> x (4 slices), 4..7 -> Wq/Wk/Wv/Wo, 8..11 -> W1 (2) + W2 (2)
__global__ void __launch_bounds__(256)
convert_all(const float* __restrict__ x,  const float* __restrict__ Wq,
            const float* __restrict__ Wk, const float* __restrict__ Wv,
            const float* __restrict__ Wo, const float* __restrict__ W1,
            const float* __restrict__ W2) {
    const float4* src; uint2* dst; int n4;
    const int seg = blockIdx.y;
    if (seg < 4) {        // x in 4 slices of 2 MB
        const int sl = seg, q = (BB*LL*DD/4)/4;
        src = (const float4*)x + (size_t)sl*q; dst = (uint2*)g_xh + (size_t)sl*q; n4 = q;
    } else if (seg == 4) { src = (const float4*)Wq; dst = (uint2*)g_wqh; n4 = DD*DD/4; }
    else if (seg == 5)   { src = (const float4*)Wk; dst = (uint2*)g_wkh; n4 = DD*DD/4; }
    else if (seg == 6)   { src = (const float4*)Wv; dst = (uint2*)g_wvh; n4 = DD*DD/4; }
    else if (seg == 7)   { src = (const float4*)Wo; dst = (uint2*)g_woh; n4 = DD*DD/4; }
    else if (seg < 10) {  // W1 in 2 slices
        const int sl = seg - 8, q = (DD*DFF/4)/2;
        src = (const float4*)W1 + (size_t)sl*q; dst = (uint2*)g_w1h + (size_t)sl*q; n4 = q;
    } else {              // W2 in 2 slices
        const int sl = seg - 10, q = (DFF*DD/4)/2;
        src = (const float4*)W2 + (size_t)sl*q; dst = (uint2*)g_w2h + (size_t)sl*q; n4 = q;
    }
    for (int i = blockIdx.x*blockDim.x + threadIdx.x; i < n4; i += gridDim.x*blockDim.x) {
        float4 v = src[i];
        dst[i] = make_uint2(packh(v.x, v.y), packh(v.z, v.w));
    }
}

// ================= LayerNorm over (L,D) jointly =================
__global__ void ln_reduce1(const float* __restrict__ x) {
    const int batch = blockIdx.y;
    const int chunk4 = (LL*DD)/(256*4);
    const float4* xp = (const float4*)(x + (size_t)batch*LL*DD) + (size_t)blockIdx.x*chunk4;
    float s = 0.f, s2 = 0.f;
    for (int i = threadIdx.x; i < chunk4; i += 256) {
        float4 v = xp[i];
        s  += v.x + v.y + v.z + v.w;
        s2 += v.x*v.x + v.y*v.y + v.z*v.z + v.w*v.w;
    }
    __shared__ float sh[256], sh2[256];
    sh[threadIdx.x] = s; sh2[threadIdx.x] = s2;
    __syncthreads();
    for (int o = 128; o > 0; o >>= 1) {
        if (threadIdx.x < o) { sh[threadIdx.x] += sh[threadIdx.x+o]; sh2[threadIdx.x] += sh2[threadIdx.x+o]; }
        __syncthreads();
    }
    if (threadIdx.x == 0) {
        g_part[(batch*256 + blockIdx.x)*2 + 0] = sh[0];
        g_part[(batch*256 + blockIdx.x)*2 + 1] = sh2[0];
    }
}

__global__ void ln_reduce2() {
    const int batch = blockIdx.x;
    __shared__ float sh[256], sh2[256];
    sh[threadIdx.x]  = g_part[(batch*256 + threadIdx.x)*2 + 0];
    sh2[threadIdx.x] = g_part[(batch*256 + threadIdx.x)*2 + 1];
    __syncthreads();
    for (int o = 128; o > 0; o >>= 1) {
        if (threadIdx.x < o) { sh[threadIdx.x] += sh[threadIdx.x+o]; sh2[threadIdx.x] += sh2[threadIdx.x+o]; }
        __syncthreads();
    }
    if (threadIdx.x == 0) {
        const float inv = 1.0f / (float)(LL*DD);
        float mu  = sh[0]  * inv;
        float var = sh2[0] * inv - mu*mu;
        g_stats[batch*2 + 0] = mu;
        g_stats[batch*2 + 1] = rsqrtf(var + EPS);
    }
}

__global__ void ln_apply_h(const float* __restrict__ x, const float* __restrict__ w,
                           const float* __restrict__ b, __half* __restrict__ out) {
    const int batch = blockIdx.y;
    const float mu   = g_stats[batch*2 + 0];
    const float rstd = g_stats[batch*2 + 1];
    const long base = (long)batch*LL*DD;
    const int n4 = LL*DD/4;
    for (int i = blockIdx.x*blockDim.x + threadIdx.x; i < n4; i += gridDim.x*blockDim.x) {
        const long idx = (long)i*4;
        float4 xv = *(const float4*)(x + base + idx);
        float4 wv = *(const float4*)(w + idx);
        float4 bv = *(const float4*)(b + idx);
        float v0 = (xv.x - mu)*rstd*wv.x + bv.x;
        float v1 = (xv.y - mu)*rstd*wv.y + bv.y;
        float v2 = (xv.z - mu)*rstd*wv.z + bv.z;
        float v3 = (xv.w - mu)*rstd*wv.w + bv.w;
        *(uint2*)(out + base + idx) = make_uint2(packh(v0, v1), packh(v2, v3));
    }
}

// ================= fp16 cp.async GEMM (128x128, warp 64x32, 4-stage) =================
#define ASTR 48
#define OFF_A1 6144
#define OFF_B  12288
#define BSTR 272
#define BSUB 4352
#define STAGE 20992
#define SMEM_GEMM4 (4*STAGE)

template<int EPI, int OUTH>
__device__ __forceinline__ void gemm_body(
    const __half* __restrict__ A, const __half* __restrict__ W,
    const float* __restrict__ bias, const float* __restrict__ R,
    float* __restrict__ C, __half* __restrict__ Ch, int N, int K, char* sm)
{
    const uint32_t sbase = smem_u32(sm);
    const int t = threadIdx.x;
    const int lane = t & 31, wid = t >> 5;
    const int g = lane >> 2, tig = lane & 3;
    const int wm = wid >> 2, wn = wid & 3;
    const int bm = blockIdx.y * 128, bn = blockIdx.x * 128;

    const int ar = t >> 1, aq = t & 1;
    const int br = t >> 4, bc = (t & 15) * 8;

    const __half* Agp = A + (size_t)(bm + ar) * K + aq * 8;
    const __half* Bgp = W + (size_t)br * N + bn + bc;

    const uint32_t a_sts = (uint32_t)ar * ASTR + (uint32_t)aq * 16;
    const uint32_t b_sts = (uint32_t)br * BSTR + (uint32_t)bc * 2;

    const uint32_t a_base = sbase + (uint32_t)(wm*64 + (lane & 15)) * ASTR + ((lane >> 4) & 1) * 16;
    const uint32_t b_base = sbase + OFF_B + (uint32_t)(lane & 15) * BSTR + (uint32_t)wn * 64 + ((lane >> 4) & 1) * 16;

    float acc[4][4][4];
    #pragma unroll
    for (int i = 0; i < 4; i++)
        #pragma unroll
        for (int j = 0; j < 4; j++)
            #pragma unroll
            for (int c = 0; c < 4; c++) acc[i][j][c] = 0.f;

    const int nk = K / 32;

    auto issue = [&](int s) {
        const uint32_t sb = sbase + (uint32_t)(s & 3) * STAGE;
        const int k0 = s * 32;
        cpa16(sb + a_sts,          Agp + k0);
        cpa16(sb + OFF_A1 + a_sts, Agp + k0 + 16);
        cpa16(sb + OFF_B + b_sts,        Bgp + (size_t)k0 * N);
        cpa16(sb + OFF_B + b_sts + BSUB, Bgp + (size_t)(k0 + 16) * N);
    };

    issue(0); CP_COMMIT();
    if (nk > 1) issue(1);
    CP_COMMIT();
    if (nk > 2) issue(2);
    CP_COMMIT();

    for (int s = 0; s < nk; s++) {
        CP_WAIT2();
        __syncthreads();
        if (s + 3 < nk) issue(s + 3);
        CP_COMMIT();

        const uint32_t so = (uint32_t)(s & 3) * STAGE;
        #pragma unroll
        for (int ks = 0; ks < 2; ks++) {
            uint32_t ah[4][4], bf[2][4];
            #pragma unroll
            for (int i = 0; i < 4; i++)
                LDSM_X4(ah[i], a_base + so + ks*OFF_A1 + i*(16*ASTR));
            #pragma unroll
            for (int j2 = 0; j2 < 2; j2++)
                LDSM_X4T(bf[j2], b_base + so + ks*BSUB + j2*32);
            #pragma unroll
            for (int i = 0; i < 4; i++)
                #pragma unroll
                for (int j = 0; j < 4; j++)
                    MMAH16816(acc[i][j], ah[i], bf[j>>1][(j&1)*2], bf[j>>1][(j&1)*2+1]);
        }
    }

    #pragma unroll
    for (int i = 0; i < 4; i++) {
        const int row0 = bm + wm*64 + i*16 + g;
        #pragma unroll
        for (int j = 0; j < 4; j++) {
            const int col0 = bn + wn*32 + j*8 + 2*tig;
            float2 bs = *(const float2*)(bias + col0);
            float2 c01 = make_float2(acc[i][j][0] + bs.x, acc[i][j][1] + bs.y);
            float2 c23 = make_float2(acc[i][j][2] + bs.x, acc[i][j][3] + bs.y);
            if (EPI == 1) {
                c01.x = fmaxf(c01.x, 0.f); c01.y = fmaxf(c01.y, 0.f);
                c23.x = fmaxf(c23.x, 0.f); c23.y = fmaxf(c23.y, 0.f);
            }
            if (EPI == 2) {
                float2 r0 = *(const float2*)(R + (size_t)row0 * N + col0);
                float2 r1 = *(const float2*)(R + (size_t)(row0+8) * N + col0);
                c01.x += r0.x; c01.y += r0.y;
                c23.x += r1.x; c23.y += r1.y;
            }
            if (EPI == 3) {
                c01.x *= SCQ; c01.y *= SCQ; c23.x *= SCQ; c23.y *= SCQ;
            }
            if (OUTH == 0) {
                *(float2*)(C + (size_t)row0 * N + col0)     = c01;
                *(float2*)(C + (size_t)(row0+8) * N + col0) = c23;
            } else {
                *(uint32_t*)(Ch + (size_t)row0 * N + col0)     = packh(c01.x, c01.y);
                *(uint32_t*)(Ch + (size_t)(row0+8) * N + col0) = packh(c23.x, c23.y);
            }
        }
    }
}

template<int EPI, int OUTH>
__global__ void __launch_bounds__(256)
tgemm(const __half* __restrict__ A, const __half* __restrict__ W,
      const float* __restrict__ bias, const float* __restrict__ R,
      float* __restrict__ C, __half* __restrict__ Ch, int N, int K)
{
    extern __shared__ __align__(128) char sm[];
    gemm_body<EPI, OUTH>(A, W, bias, R, C, Ch, N, K, sm);
}

__global__ void __launch_bounds__(256)
qkv_gemm(const float* __restrict__ bq, const float* __restrict__ bk,
         const float* __restrict__ bv)
{
    extern __shared__ __align__(128) char sm[];
    const int z = blockIdx.z;
    if (z == 0) {
        gemm_body<3,1>(g_xh,   g_wqh, bq, nullptr, nullptr, g_qh, DD, DD, sm);
    } else if (z == 1) {
        gemm_body<0,1>(g_lnyh, g_wkh, bk, nullptr, nullptr, g_kh, DD, DD, sm);
    } else {
        gemm_body<0,1>(g_lnyh, g_wvh, bv, nullptr, nullptr, g_vh, DD, DD, sm);
    }
}

// ================= V suffix sums (fp16 V, 2 blocks per bh) =================
__global__ void __launch_bounds__(1024) vsuffix_kernel() {
    const int bh = blockIdx.x >> 1;
    const int half = blockIdx.x & 1;
    const int b = bh / HH, h = bh % HH;
    const int d = half * 32 + (threadIdx.x & 31);
    const int seg = threadIdx.x >> 5;
    const int SEGK = LL / 32;
    __shared__ float part[32][32];
    const size_t vbase = (size_t)b*LL*DD + (size_t)h*DKK + d;
    const int k0 = seg * SEGK;
    float s = 0.f;
    for (int k = k0; k < k0 + SEGK; k++) s += __half2float(g_vh[vbase + (size_t)k*DD]);
    part[seg][threadIdx.x & 31] = s;
    __syncthreads();
    float acc = 0.f;
    for (int ss = seg + 1; ss < 32; ss++) acc += part[ss][threadIdx.x & 31];
    const size_t sb = (size_t)bh*LL*DKK + d;
    for (int k = k0 + SEGK - 1; k >= k0; k--) {
        g_vsuf[sb + (size_t)k*DKK] = acc;
        acc += __half2float(g_vh[vbase + (size_t)k*DD]);
    }
}

// ================= fp16 flash attention, 128 q-rows x 64-key chunks, 8 warps (R14) =================
#define TSTR 144
#define QT128 (128*TSTR)
#define CHT   (64*TSTR)

__global__ void __launch_bounds__(256)
fattn_kernel() {
    __shared__ __align__(16) char smr[QT128 + 2*CHT];
    const uint32_t sQ = smem_u32(smr);
    const uint32_t sK = sQ + QT128;
    const uint32_t sV = sK + CHT;

    const int b = blockIdx.z, h = blockIdx.y;
    const int qt = gridDim.x - 1 - blockIdx.x;   // heavy tiles first
    const int q0 = qt * 128;
    const int t = threadIdx.x, w = t >> 5, lane = t & 31;
    const int g = lane >> 2, tg = lane & 3;

    // ---- load Q tile (128 rows; fp16, pre-scaled) ----
    {
        const int r = t >> 1, hf = t & 1;
        const __half* qp = g_qh + ((size_t)(b*LL + q0 + r))*DD + h*DKK + hf*32;
        const uint32_t dq = sQ + (uint32_t)r*TSTR + hf*64;
        uint4 v0 = *(const uint4*)(qp);
        uint4 v1 = *(const uint4*)(qp + 8);
        uint4 v2 = *(const uint4*)(qp + 16);
        uint4 v3 = *(const uint4*)(qp + 24);
        STS128U(dq,      v0.x, v0.y, v0.z, v0.w);
        STS128U(dq + 16, v1.x, v1.y, v1.z, v1.w);
        STS128U(dq + 32, v2.x, v2.y, v2.z, v2.w);
        STS128U(dq + 48, v3.x, v3.y, v3.z, v3.w);
    }
    __syncthreads();

    const int mi = lane >> 3, li = lane & 7;
    uint32_t qh[4][4];
    {
        const uint32_t ro = (uint32_t)(w*16 + ((mi&1)<<3) + li) * TSTR + (uint32_t)((mi>>1)<<4);
        #pragma unroll
        for (int kc4 = 0; kc4 < 4; kc4++)
            LDSM_X4(qh[kc4], sQ + ro + kc4*32);
    }

    float oacc[8][4];
    #pragma unroll
    for (int f = 0; f < 8; f++)
        #pragma unroll
        for (int c = 0; c < 4; c++) oacc[f][c] = 0.f;
    float ls0 = 0.f, ls1 = 0.f;

    const int nch = 2*qt + 2;
    const int wrow_max = q0 + w*16 + 15;

    for (int ci = 0; ci < nch; ci++) {
        const int kc = ci * 64;
        __syncthreads();
        // ---- load K and V chunk (64 rows; 256 threads, 32B each per tensor) ----
        {
            const int r = t >> 2, qd = t & 3;
            const size_t gbase = ((size_t)(b*LL + kc + r))*DD + h*DKK + qd*16;
            const __half* kp = g_kh + gbase;
            const uint32_t dk = sK + (uint32_t)r*TSTR + qd*32;
            uint4 v0 = *(const uint4*)(kp);
            uint4 v1 = *(const uint4*)(kp + 8);
            STS128U(dk,      v0.x, v0.y, v0.z, v0.w);
            STS128U(dk + 16, v1.x, v1.y, v1.z, v1.w);
            const __half* vp = g_vh + gbase;
            const uint32_t dv = sV + (uint32_t)r*TSTR + qd*32;
            v0 = *(const uint4*)(vp);
            v1 = *(const uint4*)(vp + 8);
            STS128U(dv,      v0.x, v0.y, v0.z, v0.w);
            STS128U(dv + 16, v1.x, v1.y, v1.z, v1.w);
        }
        __syncthreads();

        if (kc > wrow_max) continue;

        // ---- S = Q K^T (fp16) ----
        float sacc[8][4];
        #pragma unroll
        for (int f = 0; f < 8; f++)
            #pragma unroll
            for (int c = 0; c < 4; c++) sacc[f][c] = 0.f;

        #pragma unroll
        for (int kc4 = 0; kc4 < 4; kc4++) {
            uint32_t bk[8][2];
            #pragma unroll
            for (int j2 = 0; j2 < 4; j2++) {
                uint32_t tmp[4];
                const uint32_t ro = (uint32_t)((2*j2 + (mi>>1))*8 + li) * TSTR
                                  + (uint32_t)(kc4*32 + (mi&1)*16);
                LDSM_X4(tmp, sK + ro);
                bk[2*j2][0] = tmp[0]; bk[2*j2][1] = tmp[1];
                bk[2*j2+1][0] = tmp[2]; bk[2*j2+1][1] = tmp[3];
            }
            #pragma unroll
            for (int f = 0; f < 8; f++) MMAH16816(sacc[f], qh[kc4], bk[f][0], bk[f][1]);
        }

        // ---- P = exp2(S), causal zero-mask on diagonal overlap ----
        const int row0 = q0 + w*16 + g;
        if (kc + 63 > row0 + 8) {
            #pragma unroll
            for (int f = 0; f < 8; f++) {
                const int col = kc + f*8 + 2*tg;
                sacc[f][0] = (col   <= row0)   ? exp2f(sacc[f][0]) : 0.f;
                sacc[f][1] = (col+1 <= row0)   ? exp2f(sacc[f][1]) : 0.f;
                sacc[f][2] = (col   <= row0+8) ? exp2f(sacc[f][2]) : 0.f;
                sacc[f][3] = (col+1 <= row0+8) ? exp2f(sacc[f][3]) : 0.f;
            }
        } else {
            #pragma unroll
            for (int f = 0; f < 8; f++) {
                sacc[f][0] = exp2f(sacc[f][0]);
                sacc[f][1] = exp2f(sacc[f][1]);
                sacc[f][2] = exp2f(sacc[f][2]);
                sacc[f][3] = exp2f(sacc[f][3]);
            }
        }
        #pragma unroll
        for (int f = 0; f < 8; f++) {
            ls0 += sacc[f][0] + sacc[f][1];
            ls1 += sacc[f][2] + sacc[f][3];
        }

        // ---- O += P V ----
        #pragma unroll
        for (int kc4 = 0; kc4 < 4; kc4++) {
            uint32_t aP[4];
            aP[0] = packh(sacc[2*kc4][0],   sacc[2*kc4][1]);
            aP[1] = packh(sacc[2*kc4][2],   sacc[2*kc4][3]);
            aP[2] = packh(sacc[2*kc4+1][0], sacc[2*kc4+1][1]);
            aP[3] = packh(sacc[2*kc4+1][2], sacc[2*kc4+1][3]);
            uint32_t bv[8][2];
            #pragma unroll
            for (int j2 = 0; j2 < 4; j2++) {
                uint32_t tmp[4];
                const uint32_t ro = (uint32_t)(kc4*16 + (mi&1)*8 + li) * TSTR
                                  + (uint32_t)((2*j2 + (mi>>1))*16);
                LDSM_X4T(tmp, sV + ro);
                bv[2*j2][0] = tmp[0]; bv[2*j2][1] = tmp[1];
                bv[2*j2+1][0] = tmp[2]; bv[2*j2+1][1] = tmp[3];
            }
            #pragma unroll
            for (int f = 0; f < 8; f++) MMAH16816(oacc[f], aP, bv[f][0], bv[f][1]);
        }
    }

    ls0 += __shfl_xor_sync(0xffffffffu, ls0, 1);
    ls0 += __shfl_xor_sync(0xffffffffu, ls0, 2);
    ls1 += __shfl_xor_sync(0xffffffffu, ls1, 1);
    ls1 += __shfl_xor_sync(0xffffffffu, ls1, 2);

    const int row0 = q0 + w*16 + g;
    const int row1 = row0 + 8;
    const float inv0 = 1.0f / (ls0 + (float)(LL - 1 - row0));
    const float inv1 = 1.0f / (ls1 + (float)(LL - 1 - row1));

    const size_t vs0 = ((size_t)((b*HH + h)*LL) + row0) * DKK;
    const size_t vs1 = ((size_t)((b*HH + h)*LL) + row1) * DKK;
    const size_t ob0 = ((size_t)(b*LL + row0))*DD + h*DKK;
    const size_t ob1 = ((size_t)(b*LL + row1))*DD + h*DKK;
    #pragma unroll
    for (int f = 0; f < 8; f++) {
        const int col = f*8 + 2*tg;
        float2 t0 = *(const float2*)(g_vsuf + vs0 + col);
        float2 t1 = *(const float2*)(g_vsuf + vs1 + col);
        *(uint32_t*)(g_atth + ob0 + col) = packh((oacc[f][0] + t0.x) * inv0, (oacc[f][1] + t0.y) * inv0);
        *(uint32_t*)(g_atth + ob1 + col) = packh((oacc[f][2] + t1.x) * inv1, (oacc[f][3] + t1.y) * inv1);
    }
}

// ================= launch =================
extern "C" void kernel_launch(void* const* d_in, const int* in_sizes, int n_in,
                              void* d_out, int out_size) {
    const float* x    = (const float*)d_in[0];
    const float* y    = (const float*)d_in[1];
    const float* Wq   = (const float*)d_in[2];
    const float* bq   = (const float*)d_in[3];
    const float* Wk   = (const float*)d_in[4];
    const float* bk   = (const float*)d_in[5];
    const float* Wv   = (const float*)d_in[6];
    const float* bv   = (const float*)d_in[7];
    const float* Wo   = (const float*)d_in[8];
    const float* bo   = (const float*)d_in[9];
    const float* W1   = (const float*)d_in[10];
    const float* b1   = (const float*)d_in[11];
    const float* W2   = (const float*)d_in[12];
    const float* b2   = (const float*)d_in[13];
    const float* ln1w = (const float*)d_in[14];
    const float* ln1b = (const float*)d_in[15];
    const float* ln2w = (const float*)d_in[16];
    const float* ln2b = (const float*)d_in[17];
    float* out = (float*)d_out;

    float *p_y1;
    cudaGetSymbolAddress((void**)&p_y1, g_y1);

    __half *lnyh,*ln1h,*atth,*hh,*woh,*w1h,*w2h;
    cudaGetSymbolAddress((void**)&lnyh, g_lnyh);
    cudaGetSymbolAddress((void**)&ln1h, g_ln1h);
    cudaGetSymbolAddress((void**)&atth, g_atth);
    cudaGetSymbolAddress((void**)&hh,   g_hh);
    cudaGetSymbolAddress((void**)&woh,  g_woh);
    cudaGetSymbolAddress((void**)&w1h,  g_w1h);
    cudaGetSymbolAddress((void**)&w2h,  g_w2h);

    cudaFuncSetAttribute(qkv_gemm,   cudaFuncAttributeMaxDynamicSharedMemorySize, SMEM_GEMM4);
    cudaFuncSetAttribute(tgemm<2,0>, cudaFuncAttributeMaxDynamicSharedMemorySize, SMEM_GEMM4);
    cudaFuncSetAttribute(tgemm<1,1>, cudaFuncAttributeMaxDynamicSharedMemorySize, SMEM_GEMM4);

    // all converts in ONE launch (12 weighted segments)
    convert_all<<<dim3(172, 12), 256>>>(x, Wq, Wk, Wv, Wo, W1, W2);

    // LN1 on y -> fp16 lny
    ln_reduce1<<<dim3(256, BB), 256>>>(y);
    ln_reduce2<<<BB, 256>>>();
    ln_apply_h<<<dim3(296, BB), 256>>>(y, ln1w, ln1b, lnyh);

    // fused Q/K/V (Q scaled fp16, K fp16, V fp16)
    qkv_gemm<<<dim3(DD/128, MM/128, 3), 256, SMEM_GEMM4>>>(bq, bk, bv);

    // suffix sums of V, then attention (writes fp16 attn)
    vsuffix_kernel<<<BB*HH*2, 1024>>>();
    fattn_kernel<<<dim3(LL/128, HH, BB), 256>>>();

    // y1 = y + attn@Wo + bo  (fp32)
    tgemm<2,0><<<dim3(DD/128, MM/128), 256, SMEM_GEMM4>>>(atth, woh, bo, y, p_y1, nullptr, DD, DD);

    // LN2 on y1 -> fp16 lny1
    ln_reduce1<<<dim3(256, BB), 256>>>(p_y1);
    ln_reduce2<<<BB, 256>>>();
    ln_apply_h<<<dim3(296, BB), 256>>>(p_y1, ln2w, ln2b, ln1h);

    // h = relu(lny1@W1 + b1) (fp16 out) ; out = y1 + h@W2 + b2 (fp32)
    tgemm<1,1><<<dim3(DFF/128, MM/128), 256, SMEM_GEMM4>>>(ln1h, w1h, b1, nullptr, nullptr, hh, DFF, DD);
    tgemm<2,0><<<dim3(DD/128,  MM/128), 256, SMEM_GEMM4>>>(hh,   w2h, b2, p_y1,    out, nullptr, DD, DFF);
}

// round 17
// speedup vs baseline: 1.0325x; 1.0173x over previous
#include <cuda_runtime.h>
#include <cuda_fp16.h>
#include <math.h>
#include <stdint.h>

#define BB 2
#define LL 2048
#define DD 1024
#define HH 16
#define DKK 64
#define DFF 4096
#define MM (BB*LL)   // 4096
#define EPS 1e-5f
#define CGX 172      // convert_all grid.x

// ================= helpers =================
__device__ __forceinline__ uint32_t smem_u32(const void* p) {
    uint32_t a;
    asm("{ .reg .u64 t; cvta.to.shared.u64 t, %1; cvt.u32.u64 %0, t; }" : "=r"(a) : "l"(p));
    return a;
}

#define LDSM_X4(r, addr) \
    asm volatile("ldmatrix.sync.aligned.m8n8.x4.shared.b16 {%0,%1,%2,%3}, [%4];" \
        : "=r"((r)[0]), "=r"((r)[1]), "=r"((r)[2]), "=r"((r)[3]) : "r"(addr))
#define LDSM_X4T(r, addr) \
    asm volatile("ldmatrix.sync.aligned.m8n8.x4.trans.shared.b16 {%0,%1,%2,%3}, [%4];" \
        : "=r"((r)[0]), "=r"((r)[1]), "=r"((r)[2]), "=r"((r)[3]) : "r"(addr))

#define MMAH16816(d, a, b0, b1) \
    asm volatile("mma.sync.aligned.m16n8k16.row.col.f32.f16.f16.f32 " \
        "{%0,%1,%2,%3}, {%4,%5,%6,%7}, {%8,%9}, {%0,%1,%2,%3};" \
        : "+f"((d)[0]), "+f"((d)[1]), "+f"((d)[2]), "+f"((d)[3]) \
        : "r"((a)[0]), "r"((a)[1]), "r"((a)[2]), "r"((a)[3]), "r"(b0), "r"(b1))

#define STS128U(addr, a, b, c, d) \
    asm volatile("st.shared.v4.b32 [%0], {%1, %2, %3, %4};" \
                 :: "r"((uint32_t)(addr)), "r"(a), "r"(b), "r"(c), "r"(d) : "memory")

__device__ __forceinline__ void cpa16(uint32_t dst, const void* src) {
    asm volatile("cp.async.cg.shared.global [%0], [%1], 16;" :: "r"(dst), "l"(src));
}
#define CP_COMMIT() asm volatile("cp.async.commit_group;" ::: "memory")
#define CP_WAIT2()  asm volatile("cp.async.wait_group 2;" ::: "memory")

__device__ __forceinline__ uint32_t packh(float x0, float x1) {
    __half2 h = __floats2half2_rn(x0, x1);
    return *reinterpret_cast<uint32_t*>(&h);
}

#define SCQ (0.125f * 1.4426950408889634f)   // 1/sqrt(64) * log2(e)

// ================= scratch =================
__device__ float g_vsuf[BB*HH*LL*DKK];
__device__ float g_y1  [BB*LL*DD];
__device__ float g_part[2048];       // LN1 partials from convert_all
__device__ float g_part2[256*2];     // LN2 partials from Wo-GEMM epilogue
__device__ float g_stats[BB*2];

// fp16 operands
__device__ __half g_xh  [BB*LL*DD];
__device__ __half g_lnyh[BB*LL*DD];
__device__ __half g_ln1h[BB*LL*DD];
__device__ __half g_qh  [BB*LL*DD];
__device__ __half g_kh  [BB*LL*DD];
__device__ __half g_vh  [BB*LL*DD];
__device__ __half g_atth[BB*LL*DD];
__device__ __half g_hh  [BB*LL*DFF];
__device__ __half g_wqh[DD*DD];
__device__ __half g_wkh[DD*DD];
__device__ __half g_wvh[DD*DD];
__device__ __half g_woh[DD*DD];
__device__ __half g_w1h[DD*DFF];
__device__ __half g_w2h[DFF*DD];

// ================= fused converts + LN1 partial sums (one launch) =================
// grid.y: 0..3 -> x (4 slices), 4..7 -> Wq/Wk/Wv/Wo, 8..9 -> W1, 10..11 -> W2,
//         12..15 -> LN1 partial sums over y (batch x half)
__global__ void __launch_bounds__(256)
convert_all(const float* __restrict__ x,  const float* __restrict__ y,
            const float* __restrict__ Wq, const float* __restrict__ Wk,
            const float* __restrict__ Wv, const float* __restrict__ Wo,
            const float* __restrict__ W1, const float* __restrict__ W2) {
    const int seg = blockIdx.y;
    const int t = threadIdx.x;
    __shared__ float sh[256], sh2[256];

    if (seg >= 12) {
        const int b = (seg - 12) >> 1, sl = (seg - 12) & 1;
        const int q4 = (LL*DD/4)/2;
        const float4* yp = (const float4*)y + (size_t)b*(LL*DD/4) + (size_t)sl*q4;
        float s = 0.f, s2 = 0.f;
        for (int i = blockIdx.x*256 + t; i < q4; i += gridDim.x*256) {
            float4 v = yp[i];
            s  += v.x + v.y + v.z + v.w;
            s2 += v.x*v.x + v.y*v.y + v.z*v.z + v.w*v.w;
        }
        sh[t] = s; sh2[t] = s2;
        __syncthreads();
        for (int o = 128; o > 0; o >>= 1) {
            if (t < o) { sh[t] += sh[t+o]; sh2[t] += sh2[t+o]; }
            __syncthreads();
        }
        if (t == 0) {
            const int slot = ((b*2 + sl)*gridDim.x + blockIdx.x);
            g_part[slot*2 + 0] = sh[0];
            g_part[slot*2 + 1] = sh2[0];
        }
        return;
    }

    const float4* src; uint2* dst; int n4;
    if (seg < 4) {
        const int sl = seg, q = (BB*LL*DD/4)/4;
        src = (const float4*)x + (size_t)sl*q; dst = (uint2*)g_xh + (size_t)sl*q; n4 = q;
    } else if (seg == 4) { src = (const float4*)Wq; dst = (uint2*)g_wqh; n4 = DD*DD/4; }
    else if (seg == 5)   { src = (const float4*)Wk; dst = (uint2*)g_wkh; n4 = DD*DD/4; }
    else if (seg == 6)   { src = (const float4*)Wv; dst = (uint2*)g_wvh; n4 = DD*DD/4; }
    else if (seg == 7)   { src = (const float4*)Wo; dst = (uint2*)g_woh; n4 = DD*DD/4; }
    else if (seg < 10) {
        const int sl = seg - 8, q = (DD*DFF/4)/2;
        src = (const float4*)W1 + (size_t)sl*q; dst = (uint2*)g_w1h + (size_t)sl*q; n4 = q;
    } else {
        const int sl = seg - 10, q = (DFF*DD/4)/2;
        src = (const float4*)W2 + (size_t)sl*q; dst = (uint2*)g_w2h + (size_t)sl*q; n4 = q;
    }
    for (int i = blockIdx.x*256 + t; i < n4; i += gridDim.x*256) {
        float4 v = src[i];
        dst[i] = make_uint2(packh(v.x, v.y), packh(v.z, v.w));
    }
}

// ================= LN stats finalizers =================
__global__ void ln1_stats() {
    const int b = blockIdx.x, t = threadIdx.x;
    float s = 0.f, s2 = 0.f;
    for (int i = t; i < 2*CGX; i += 256) {
        const int slot = b*2*CGX + i;
        s  += g_part[slot*2 + 0];
        s2 += g_part[slot*2 + 1];
    }
    __shared__ float sh[256], sh2[256];
    sh[t] = s; sh2[t] = s2;
    __syncthreads();
    for (int o = 128; o > 0; o >>= 1) {
        if (t < o) { sh[t] += sh[t+o]; sh2[t] += sh2[t+o]; }
        __syncthreads();
    }
    if (t == 0) {
        const float inv = 1.0f / (float)(LL*DD);
        float mu  = sh[0]  * inv;
        float var = sh2[0] * inv - mu*mu;
        g_stats[b*2 + 0] = mu;
        g_stats[b*2 + 1] = rsqrtf(var + EPS);
    }
}

__global__ void __launch_bounds__(128) ln2_stats() {
    const int b = blockIdx.x, t = threadIdx.x;
    __shared__ float sh[128], sh2[128];
    sh[t]  = g_part2[(b*128 + t)*2 + 0];
    sh2[t] = g_part2[(b*128 + t)*2 + 1];
    __syncthreads();
    for (int o = 64; o > 0; o >>= 1) {
        if (t < o) { sh[t] += sh[t+o]; sh2[t] += sh2[t+o]; }
        __syncthreads();
    }
    if (t == 0) {
        const float inv = 1.0f / (float)(LL*DD);
        float mu  = sh[0]  * inv;
        float var = sh2[0] * inv - mu*mu;
        g_stats[b*2 + 0] = mu;
        g_stats[b*2 + 1] = rsqrtf(var + EPS);
    }
}

__global__ void ln_apply_h(const float* __restrict__ x, const float* __restrict__ w,
                           const float* __restrict__ b, __half* __restrict__ out) {
    const int batch = blockIdx.y;
    const float mu   = g_stats[batch*2 + 0];
    const float rstd = g_stats[batch*2 + 1];
    const long base = (long)batch*LL*DD;
    const int n4 = LL*DD/4;
    for (int i = blockIdx.x*blockDim.x + threadIdx.x; i < n4; i += gridDim.x*blockDim.x) {
        const long idx = (long)i*4;
        float4 xv = *(const float4*)(x + base + idx);
        float4 wv = *(const float4*)(w + idx);
        float4 bv = *(const float4*)(b + idx);
        float v0 = (xv.x - mu)*rstd*wv.x + bv.x;
        float v1 = (xv.y - mu)*rstd*wv.y + bv.y;
        float v2 = (xv.z - mu)*rstd*wv.z + bv.z;
        float v3 = (xv.w - mu)*rstd*wv.w + bv.w;
        *(uint2*)(out + base + idx) = make_uint2(packh(v0, v1), packh(v2, v3));
    }
}

// ================= fp16 cp.async GEMM (128x128, warp 64x32, 4-stage) =================
// LNS=1: epilogue also block-reduces (sum, sumsq) of C into g_part2 (for LN2 stats)
#define ASTR 48
#define OFF_A1 6144
#define OFF_B  12288
#define BSTR 272
#define BSUB 4352
#define STAGE 20992
#define SMEM_GEMM4 (4*STAGE)

template<int EPI, int OUTH, int LNS>
__device__ __forceinline__ void gemm_body(
    const __half* __restrict__ A, const __half* __restrict__ W,
    const float* __restrict__ bias, const float* __restrict__ R,
    float* __restrict__ C, __half* __restrict__ Ch, int N, int K, char* sm)
{
    const uint32_t sbase = smem_u32(sm);
    const int t = threadIdx.x;
    const int lane = t & 31, wid = t >> 5;
    const int g = lane >> 2, tig = lane & 3;
    const int wm = wid >> 2, wn = wid & 3;
    const int bm = blockIdx.y * 128, bn = blockIdx.x * 128;

    const int ar = t >> 1, aq = t & 1;
    const int br = t >> 4, bc = (t & 15) * 8;

    const __half* Agp = A + (size_t)(bm + ar) * K + aq * 8;
    const __half* Bgp = W + (size_t)br * N + bn + bc;

    const uint32_t a_sts = (uint32_t)ar * ASTR + (uint32_t)aq * 16;
    const uint32_t b_sts = (uint32_t)br * BSTR + (uint32_t)bc * 2;

    const uint32_t a_base = sbase + (uint32_t)(wm*64 + (lane & 15)) * ASTR + ((lane >> 4) & 1) * 16;
    const uint32_t b_base = sbase + OFF_B + (uint32_t)(lane & 15) * BSTR + (uint32_t)wn * 64 + ((lane >> 4) & 1) * 16;

    float acc[4][4][4];
    #pragma unroll
    for (int i = 0; i < 4; i++)
        #pragma unroll
        for (int j = 0; j < 4; j++)
            #pragma unroll
            for (int c = 0; c < 4; c++) acc[i][j][c] = 0.f;

    const int nk = K / 32;

    auto issue = [&](int s) {
        const uint32_t sb = sbase + (uint32_t)(s & 3) * STAGE;
        const int k0 = s * 32;
        cpa16(sb + a_sts,          Agp + k0);
        cpa16(sb + OFF_A1 + a_sts, Agp + k0 + 16);
        cpa16(sb + OFF_B + b_sts,        Bgp + (size_t)k0 * N);
        cpa16(sb + OFF_B + b_sts + BSUB, Bgp + (size_t)(k0 + 16) * N);
    };

    issue(0); CP_COMMIT();
    if (nk > 1) issue(1);
    CP_COMMIT();
    if (nk > 2) issue(2);
    CP_COMMIT();

    for (int s = 0; s < nk; s++) {
        CP_WAIT2();
        __syncthreads();
        if (s + 3 < nk) issue(s + 3);
        CP_COMMIT();

        const uint32_t so = (uint32_t)(s & 3) * STAGE;
        #pragma unroll
        for (int ks = 0; ks < 2; ks++) {
            uint32_t ah[4][4], bf[2][4];
            #pragma unroll
            for (int i = 0; i < 4; i++)
                LDSM_X4(ah[i], a_base + so + ks*OFF_A1 + i*(16*ASTR));
            #pragma unroll
            for (int j2 = 0; j2 < 2; j2++)
                LDSM_X4T(bf[j2], b_base + so + ks*BSUB + j2*32);
            #pragma unroll
            for (int i = 0; i < 4; i++)
                #pragma unroll
                for (int j = 0; j < 4; j++)
                    MMAH16816(acc[i][j], ah[i], bf[j>>1][(j&1)*2], bf[j>>1][(j&1)*2+1]);
        }
    }

    float lns = 0.f, lns2 = 0.f;

    #pragma unroll
    for (int i = 0; i < 4; i++) {
        const int row0 = bm + wm*64 + i*16 + g;
        #pragma unroll
        for (int j = 0; j < 4; j++) {
            const int col0 = bn + wn*32 + j*8 + 2*tig;
            float2 bs = *(const float2*)(bias + col0);
            float2 c01 = make_float2(acc[i][j][0] + bs.x, acc[i][j][1] + bs.y);
            float2 c23 = make_float2(acc[i][j][2] + bs.x, acc[i][j][3] + bs.y);
            if (EPI == 1) {
                c01.x = fmaxf(c01.x, 0.f); c01.y = fmaxf(c01.y, 0.f);
                c23.x = fmaxf(c23.x, 0.f); c23.y = fmaxf(c23.y, 0.f);
            }
            if (EPI == 2) {
                float2 r0 = *(const float2*)(R + (size_t)row0 * N + col0);
                float2 r1 = *(const float2*)(R + (size_t)(row0+8) * N + col0);
                c01.x += r0.x; c01.y += r0.y;
                c23.x += r1.x; c23.y += r1.y;
            }
            if (EPI == 3) {
                c01.x *= SCQ; c01.y *= SCQ; c23.x *= SCQ; c23.y *= SCQ;
            }
            if (LNS) {
                lns  += c01.x + c01.y + c23.x + c23.y;
                lns2 += c01.x*c01.x + c01.y*c01.y + c23.x*c23.x + c23.y*c23.y;
            }
            if (OUTH == 0) {
                *(float2*)(C + (size_t)row0 * N + col0)     = c01;
                *(float2*)(C + (size_t)(row0+8) * N + col0) = c23;
            } else {
                *(uint32_t*)(Ch + (size_t)row0 * N + col0)     = packh(c01.x, c01.y);
                *(uint32_t*)(Ch + (size_t)(row0+8) * N + col0) = packh(c23.x, c23.y);
            }
        }
    }

    if (LNS) {
        float* shf = (float*)sm;   // ring no longer needed
        __syncthreads();
        shf[t] = lns; shf[256 + t] = lns2;
        __syncthreads();
        for (int o = 128; o > 0; o >>= 1) {
            if (t < o) { shf[t] += shf[t+o]; shf[256+t] += shf[256+t+o]; }
            __syncthreads();
        }
        if (t == 0) {
            const int batch = bm >> 11;                          // bm / 2048
            const int slot = batch*128 + ((blockIdx.y & 15) * gridDim.x + blockIdx.x);
            g_part2[slot*2 + 0] = shf[0];
            g_part2[slot*2 + 1] = shf[256];
        }
    }
}

template<int EPI, int OUTH, int LNS>
__global__ void __launch_bounds__(256)
tgemm(const __half* __restrict__ A, const __half* __restrict__ W,
      const float* __restrict__ bias, const float* __restrict__ R,
      float* __restrict__ C, __half* __restrict__ Ch, int N, int K)
{
    extern __shared__ __align__(128) char sm[];
    gemm_body<EPI, OUTH, LNS>(A, W, bias, R, C, Ch, N, K, sm);
}

__global__ void __launch_bounds__(256)
qkv_gemm(const float* __restrict__ bq, const float* __restrict__ bk,
         const float* __restrict__ bv)
{
    extern __shared__ __align__(128) char sm[];
    const int z = blockIdx.z;
    if (z == 0) {
        gemm_body<3,1,0>(g_xh,   g_wqh, bq, nullptr, nullptr, g_qh, DD, DD, sm);
    } else if (z == 1) {
        gemm_body<0,1,0>(g_lnyh, g_wkh, bk, nullptr, nullptr, g_kh, DD, DD, sm);
    } else {
        gemm_body<0,1,0>(g_lnyh, g_wvh, bv, nullptr, nullptr, g_vh, DD, DD, sm);
    }
}

// ================= V suffix sums (fp16 V, 2 blocks per bh) =================
__global__ void __launch_bounds__(1024) vsuffix_kernel() {
    const int bh = blockIdx.x >> 1;
    const int half = blockIdx.x & 1;
    const int b = bh / HH, h = bh % HH;
    const int d = half * 32 + (threadIdx.x & 31);
    const int seg = threadIdx.x >> 5;
    const int SEGK = LL / 32;
    __shared__ float part[32][32];
    const size_t vbase = (size_t)b*LL*DD + (size_t)h*DKK + d;
    const int k0 = seg * SEGK;
    float s = 0.f;
    for (int k = k0; k < k0 + SEGK; k++) s += __half2float(g_vh[vbase + (size_t)k*DD]);
    part[seg][threadIdx.x & 31] = s;
    __syncthreads();
    float acc = 0.f;
    for (int ss = seg + 1; ss < 32; ss++) acc += part[ss][threadIdx.x & 31];
    const size_t sb = (size_t)bh*LL*DKK + d;
    for (int k = k0 + SEGK - 1; k >= k0; k--) {
        g_vsuf[sb + (size_t)k*DKK] = acc;
        acc += __half2float(g_vh[vbase + (size_t)k*DD]);
    }
}

// ================= fp16 flash attention, 128 q-rows x 64-key chunks, 8 warps =================
#define TSTR 144
#define QT128 (128*TSTR)
#define CHT   (64*TSTR)

__global__ void __launch_bounds__(256)
fattn_kernel() {
    __shared__ __align__(16) char smr[QT128 + 2*CHT];
    const uint32_t sQ = smem_u32(smr);
    const uint32_t sK = sQ + QT128;
    const uint32_t sV = sK + CHT;

    const int b = blockIdx.z, h = blockIdx.y;
    const int qt = gridDim.x - 1 - blockIdx.x;   // heavy tiles first
    const int q0 = qt * 128;
    const int t = threadIdx.x, w = t >> 5, lane = t & 31;
    const int g = lane >> 2, tg = lane & 3;

    {
        const int r = t >> 1, hf = t & 1;
        const __half* qp = g_qh + ((size_t)(b*LL + q0 + r))*DD + h*DKK + hf*32;
        const uint32_t dq = sQ + (uint32_t)r*TSTR + hf*64;
        uint4 v0 = *(const uint4*)(qp);
        uint4 v1 = *(const uint4*)(qp + 8);
        uint4 v2 = *(const uint4*)(qp + 16);
        uint4 v3 = *(const uint4*)(qp + 24);
        STS128U(dq,      v0.x, v0.y, v0.z, v0.w);
        STS128U(dq + 16, v1.x, v1.y, v1.z, v1.w);
        STS128U(dq + 32, v2.x, v2.y, v2.z, v2.w);
        STS128U(dq + 48, v3.x, v3.y, v3.z, v3.w);
    }
    __syncthreads();

    const int mi = lane >> 3, li = lane & 7;
    uint32_t qh[4][4];
    {
        const uint32_t ro = (uint32_t)(w*16 + ((mi&1)<<3) + li) * TSTR + (uint32_t)((mi>>1)<<4);
        #pragma unroll
        for (int kc4 = 0; kc4 < 4; kc4++)
            LDSM_X4(qh[kc4], sQ + ro + kc4*32);
    }

    float oacc[8][4];
    #pragma unroll
    for (int f = 0; f < 8; f++)
        #pragma unroll
        for (int c = 0; c < 4; c++) oacc[f][c] = 0.f;
    float ls0 = 0.f, ls1 = 0.f;

    const int nch = 2*qt + 2;
    const int wrow_max = q0 + w*16 + 15;

    for (int ci = 0; ci < nch; ci++) {
        const int kc = ci * 64;
        __syncthreads();
        {
            const int r = t >> 2, qd = t & 3;
            const size_t gbase = ((size_t)(b*LL + kc + r))*DD + h*DKK + qd*16;
            const __half* kp = g_kh + gbase;
            const uint32_t dk = sK + (uint32_t)r*TSTR + qd*32;
            uint4 v0 = *(const uint4*)(kp);
            uint4 v1 = *(const uint4*)(kp + 8);
            STS128U(dk,      v0.x, v0.y, v0.z, v0.w);
            STS128U(dk + 16, v1.x, v1.y, v1.z, v1.w);
            const __half* vp = g_vh + gbase;
            const uint32_t dv = sV + (uint32_t)r*TSTR + qd*32;
            v0 = *(const uint4*)(vp);
            v1 = *(const uint4*)(vp + 8);
            STS128U(dv,      v0.x, v0.y, v0.z, v0.w);
            STS128U(dv + 16, v1.x, v1.y, v1.z, v1.w);
        }
        __syncthreads();

        if (kc > wrow_max) continue;

        float sacc[8][4];
        #pragma unroll
        for (int f = 0; f < 8; f++)
            #pragma unroll
            for (int c = 0; c < 4; c++) sacc[f][c] = 0.f;

        #pragma unroll
        for (int kc4 = 0; kc4 < 4; kc4++) {
            uint32_t bk[8][2];
            #pragma unroll
            for (int j2 = 0; j2 < 4; j2++) {
                uint32_t tmp[4];
                const uint32_t ro = (uint32_t)((2*j2 + (mi>>1))*8 + li) * TSTR
                                  + (uint32_t)(kc4*32 + (mi&1)*16);
                LDSM_X4(tmp, sK + ro);
                bk[2*j2][0] = tmp[0]; bk[2*j2][1] = tmp[1];
                bk[2*j2+1][0] = tmp[2]; bk[2*j2+1][1] = tmp[3];
            }
            #pragma unroll
            for (int f = 0; f < 8; f++) MMAH16816(sacc[f], qh[kc4], bk[f][0], bk[f][1]);
        }

        const int row0 = q0 + w*16 + g;
        if (kc + 63 > row0 + 8) {
            #pragma unroll
            for (int f = 0; f < 8; f++) {
                const int col = kc + f*8 + 2*tg;
                sacc[f][0] = (col   <= row0)   ? exp2f(sacc[f][0]) : 0.f;
                sacc[f][1] = (col+1 <= row0)   ? exp2f(sacc[f][1]) : 0.f;
                sacc[f][2] = (col   <= row0+8) ? exp2f(sacc[f][2]) : 0.f;
                sacc[f][3] = (col+1 <= row0+8) ? exp2f(sacc[f][3]) : 0.f;
            }
        } else {
            #pragma unroll
            for (int f = 0; f < 8; f++) {
                sacc[f][0] = exp2f(sacc[f][0]);
                sacc[f][1] = exp2f(sacc[f][1]);
                sacc[f][2] = exp2f(sacc[f][2]);
                sacc[f][3] = exp2f(sacc[f][3]);
            }
        }
        #pragma unroll
        for (int f = 0; f < 8; f++) {
            ls0 += sacc[f][0] + sacc[f][1];
            ls1 += sacc[f][2] + sacc[f][3];
        }

        #pragma unroll
        for (int kc4 = 0; kc4 < 4; kc4++) {
            uint32_t aP[4];
            aP[0] = packh(sacc[2*kc4][0],   sacc[2*kc4][1]);
            aP[1] = packh(sacc[2*kc4][2],   sacc[2*kc4][3]);
            aP[2] = packh(sacc[2*kc4+1][0], sacc[2*kc4+1][1]);
            aP[3] = packh(sacc[2*kc4+1][2], sacc[2*kc4+1][3]);
            uint32_t bv[8][2];
            #pragma unroll
            for (int j2 = 0; j2 < 4; j2++) {
                uint32_t tmp[4];
                const uint32_t ro = (uint32_t)(kc4*16 + (mi&1)*8 + li) * TSTR
                                  + (uint32_t)((2*j2 + (mi>>1))*16);
                LDSM_X4T(tmp, sV + ro);
                bv[2*j2][0] = tmp[0]; bv[2*j2][1] = tmp[1];
                bv[2*j2+1][0] = tmp[2]; bv[2*j2+1][1] = tmp[3];
            }
            #pragma unroll
            for (int f = 0; f < 8; f++) MMAH16816(oacc[f], aP, bv[f][0], bv[f][1]);
        }
    }

    ls0 += __shfl_xor_sync(0xffffffffu, ls0, 1);
    ls0 += __shfl_xor_sync(0xffffffffu, ls0, 2);
    ls1 += __shfl_xor_sync(0xffffffffu, ls1, 1);
    ls1 += __shfl_xor_sync(0xffffffffu, ls1, 2);

    const int row0 = q0 + w*16 + g;
    const int row1 = row0 + 8;
    const float inv0 = 1.0f / (ls0 + (float)(LL - 1 - row0));
    const float inv1 = 1.0f / (ls1 + (float)(LL - 1 - row1));

    const size_t vs0 = ((size_t)((b*HH + h)*LL) + row0) * DKK;
    const size_t vs1 = ((size_t)((b*HH + h)*LL) + row1) * DKK;
    const size_t ob0 = ((size_t)(b*LL + row0))*DD + h*DKK;
    const size_t ob1 = ((size_t)(b*LL + row1))*DD + h*DKK;
    #pragma unroll
    for (int f = 0; f < 8; f++) {
        const int col = f*8 + 2*tg;
        float2 t0 = *(const float2*)(g_vsuf + vs0 + col);
        float2 t1 = *(const float2*)(g_vsuf + vs1 + col);
        *(uint32_t*)(g_atth + ob0 + col) = packh((oacc[f][0] + t0.x) * inv0, (oacc[f][1] + t0.y) * inv0);
        *(uint32_t*)(g_atth + ob1 + col) = packh((oacc[f][2] + t1.x) * inv1, (oacc[f][3] + t1.y) * inv1);
    }
}

// ================= launch =================
extern "C" void kernel_launch(void* const* d_in, const int* in_sizes, int n_in,
                              void* d_out, int out_size) {
    const float* x    = (const float*)d_in[0];
    const float* y    = (const float*)d_in[1];
    const float* Wq   = (const float*)d_in[2];
    const float* bq   = (const float*)d_in[3];
    const float* Wk   = (const float*)d_in[4];
    const float* bk   = (const float*)d_in[5];
    const float* Wv   = (const float*)d_in[6];
    const float* bv   = (const float*)d_in[7];
    const float* Wo   = (const float*)d_in[8];
    const float* bo   = (const float*)d_in[9];
    const float* W1   = (const float*)d_in[10];
    const float* b1   = (const float*)d_in[11];
    const float* W2   = (const float*)d_in[12];
    const float* b2   = (const float*)d_in[13];
    const float* ln1w = (const float*)d_in[14];
    const float* ln1b = (const float*)d_in[15];
    const float* ln2w = (const float*)d_in[16];
    const float* ln2b = (const float*)d_in[17];
    float* out = (float*)d_out;

    float *p_y1;
    cudaGetSymbolAddress((void**)&p_y1, g_y1);

    __half *lnyh,*ln1h,*atth,*hh,*woh,*w1h,*w2h;
    cudaGetSymbolAddress((void**)&lnyh, g_lnyh);
    cudaGetSymbolAddress((void**)&ln1h, g_ln1h);
    cudaGetSymbolAddress((void**)&atth, g_atth);
    cudaGetSymbolAddress((void**)&hh,   g_hh);
    cudaGetSymbolAddress((void**)&woh,  g_woh);
    cudaGetSymbolAddress((void**)&w1h,  g_w1h);
    cudaGetSymbolAddress((void**)&w2h,  g_w2h);

    cudaFuncSetAttribute(qkv_gemm,     cudaFuncAttributeMaxDynamicSharedMemorySize, SMEM_GEMM4);
    cudaFuncSetAttribute(tgemm<2,0,1>, cudaFuncAttributeMaxDynamicSharedMemorySize, SMEM_GEMM4);
    cudaFuncSetAttribute(tgemm<2,0,0>, cudaFuncAttributeMaxDynamicSharedMemorySize, SMEM_GEMM4);
    cudaFuncSetAttribute(tgemm<1,1,0>, cudaFuncAttributeMaxDynamicSharedMemorySize, SMEM_GEMM4);

    // converts + LN1 partial sums in ONE launch
    convert_all<<<dim3(CGX, 16), 256>>>(x, y, Wq, Wk, Wv, Wo, W1, W2);
    ln1_stats<<<BB, 256>>>();
    ln_apply_h<<<dim3(296, BB), 256>>>(y, ln1w, ln1b, lnyh);

    // fused Q/K/V (Q scaled fp16, K fp16, V fp16)
    qkv_gemm<<<dim3(DD/128, MM/128, 3), 256, SMEM_GEMM4>>>(bq, bk, bv);

    // suffix sums of V, then attention (writes fp16 attn)
    vsuffix_kernel<<<BB*HH*2, 1024>>>();
    fattn_kernel<<<dim3(LL/128, HH, BB), 256>>>();

    // y1 = y + attn@Wo + bo  (fp32) + LN2 partial stats in epilogue
    tgemm<2,0,1><<<dim3(DD/128, MM/128), 256, SMEM_GEMM4>>>(atth, woh, bo, y, p_y1, nullptr, DD, DD);
    ln2_stats<<<BB, 128>>>();
    ln_apply_h<<<dim3(296, BB), 256>>>(p_y1, ln2w, ln2b, ln1h);

    // h = relu(lny1@W1 + b1) (fp16 out) ; out = y1 + h@W2 + b2 (fp32)
    tgemm<1,1,0><<<dim3(DFF/128, MM/128), 256, SMEM_GEMM4>>>(ln1h, w1h, b1, nullptr, nullptr, hh, DFF, DD);
    tgemm<2,0,0><<<dim3(DD/128,  MM/128), 256, SMEM_GEMM4>>>(hh,   w2h, b2, p_y1,    out, nullptr, DD, DFF);
}